// round 7
// baseline (speedup 1.0000x reference)
#include <cuda_runtime.h>
#include <cstdint>

// Fixed shape: stimuli [4,32,304,608,1] fp32, eye [4,32,2,3]
constexpr int H  = 304;
constexpr int W  = 608;
constexpr int HW = H * W;
constexpr int NFRAMES = 128;

// Block output tile: 32 cols x 16 rows. 4 warps, each warp 8x4 px per iter, 4 iters.
constexpr int BTC = 32;
constexpr int BTR = 16;
constexpr int COL_TILES = W / BTC;      // 19
constexpr int ROW_TILES = H / BTR;      // 19
constexpr int BLOCKS_X  = COL_TILES * ROW_TILES;  // 361
constexpr int THREADS   = 128;
constexpr int ITERS     = 4;
constexpr int SMEM_FLOATS = 6144;       // 24 KB staging buffer

__device__ __forceinline__ float lin_x(int col) {
    // jnp.linspace(-1,1,W): v[i] = fl(-1 + fl(i*step)), endpoint exactly 1.0
    const float step_x = 2.0f / (float)(W - 1);
    return (col == W - 1) ? 1.0f
         : __fadd_rn(-1.0f, __fmul_rn((float)col, step_x));
}
__device__ __forceinline__ float lin_y(int row) {
    const float step_y = 2.0f / (float)(H - 1);
    return (row == H - 1) ? 1.0f
         : __fadd_rn(-1.0f, __fmul_rn((float)row, step_y));
}

// Exact source coords used everywhere (einsum k-order fmuladd chain)
__device__ __forceinline__ void src_xy(float a00, float a01, float a02,
                                       float a10, float a11, float a12,
                                       int row, int col, float& x, float& y) {
    const float xt = lin_x(col);
    const float yt = lin_y(row);
    const float Tx = __fadd_rn(__fmaf_rn(a01, yt, __fmul_rn(a00, xt)), a02);
    const float Ty = __fadd_rn(__fmaf_rn(a11, yt, __fmul_rn(a10, xt)), a12);
    x = __fmul_rn(__fadd_rn(Tx, 1.0f), (float)W * 0.5f);
    y = __fmul_rn(__fadd_rn(Ty, 1.0f), (float)H * 0.5f);
}

// Blend with the reference's exact FP sequence
__device__ __forceinline__ float blend(float x, float y,
                                       int x0, int x1, int y0, int y1,
                                       float Ia, float Ib, float Ic, float Id) {
    const float dx1 = __fsub_rn((float)x1, x);
    const float dx0 = __fsub_rn(x, (float)x0);
    const float dy1 = __fsub_rn((float)y1, y);
    const float dy0 = __fsub_rn(y, (float)y0);
    const float wa = __fmul_rn(dx1, dy1);
    const float wb = __fmul_rn(dx1, dy0);
    const float wc = __fmul_rn(dx0, dy1);
    const float wd = __fmul_rn(dx0, dy0);
    const float p1 = __fmul_rn(wa, Ia);
    const float p2 = __fmul_rn(wb, Ib);
    const float p3 = __fmul_rn(wc, Ic);
    const float p4 = __fmul_rn(wd, Id);
    return __fadd_rn(__fadd_rn(__fadd_rn(p1, p2), p3), p4);
}

__global__ __launch_bounds__(THREADS) void warp_bilinear_kernel(
    const float* __restrict__ stimuli,
    const float* __restrict__ eye,
    float* __restrict__ out)
{
    __shared__ float box[SMEM_FLOATS];

    const int n  = blockIdx.y;
    const int bt = blockIdx.x;
    const int rt = bt / COL_TILES;
    const int ct = bt - rt * COL_TILES;
    const int col0 = ct * BTC;
    const int row0 = rt * BTR;

    const int wid  = threadIdx.x >> 5;
    const int lane = threadIdx.x & 31;

    const float* a = eye + (size_t)n * 6;
    const float a00 = __ldg(a + 0);
    const float a01 = __ldg(a + 1);
    const float a02 = __ldg(a + 2);
    const float a10 = __ldg(a + 3);
    const float a11 = __ldg(a + 4);
    const float a12 = __ldg(a + 5);

    const float* __restrict__ img = stimuli + (size_t)n * HW;
    float* __restrict__       dst = out     + (size_t)n * HW;

    // Per-thread output coords: warp covers 8 cols x 4 rows, 4 warps along x.
    const int col = col0 + wid * 8 + (lane & 7);
    const int rb  = row0 + (lane >> 3);

    // ---- Source bounding box from the 4 tile corners (map monotone per axis;
    //      +-1/+2 px margin covers rounding and the +1 neighbor) ----
    float cx0, cy0, cx1, cy1, cx2, cy2, cx3, cy3;
    src_xy(a00, a01, a02, a10, a11, a12, row0,           col0,           cx0, cy0);
    src_xy(a00, a01, a02, a10, a11, a12, row0,           col0 + BTC - 1, cx1, cy1);
    src_xy(a00, a01, a02, a10, a11, a12, row0 + BTR - 1, col0,           cx2, cy2);
    src_xy(a00, a01, a02, a10, a11, a12, row0 + BTR - 1, col0 + BTC - 1, cx3, cy3);

    const float xmin = fminf(fminf(cx0, cx1), fminf(cx2, cx3));
    const float xmax = fmaxf(fmaxf(cx0, cx1), fmaxf(cx2, cx3));
    const float ymin = fminf(fminf(cy0, cy1), fminf(cy2, cy3));
    const float ymax = fmaxf(fmaxf(cy0, cy1), fmaxf(cy2, cy3));

    const int bx0 = min(max((int)floorf(xmin) - 1, 0), W - 1);
    const int bx1 = min(max((int)floorf(xmax) + 2, 0), W - 1);
    const int by0 = min(max((int)floorf(ymin) - 1, 0), H - 1);
    const int by1 = min(max((int)floorf(ymax) + 2, 0), H - 1);

    const int bw    = bx1 - bx0 + 1;
    const int bh    = by1 - by0 + 1;
    const int pitch = bw | 1;                 // odd pitch -> decorrelate banks
    const bool use_smem = (pitch * bh <= SMEM_FLOATS);

    if (use_smem) {
        // Coalesced staging of the bbox
        for (int r = wid; r < bh; r += 4) {
            const float* srow = img + (by0 + r) * W + bx0;
            float* drow = box + r * pitch;
            for (int c = lane; c < bw; c += 32)
                drow[c] = __ldg(srow + c);
        }
        __syncthreads();

#pragma unroll
        for (int i = 0; i < ITERS; ++i) {
            const int row = rb + i * 4;
            float x, y;
            src_xy(a00, a01, a02, a10, a11, a12, row, col, x, y);

            const int x0u = (int)floorf(x);
            const int y0u = (int)floorf(y);
            const int x0 = min(max(x0u, 0), W - 1);
            const int x1 = min(max(x0u + 1, 0), W - 1);
            const int y0 = min(max(y0u, 0), H - 1);
            const int y1 = min(max(y0u + 1, 0), H - 1);

            const int sA = (y0 - by0) * pitch - bx0;
            const int sB = (y1 - by0) * pitch - bx0;

            const float Ia = box[sA + x0];
            const float Ib = box[sB + x0];
            const float Ic = box[sA + x1];
            const float Id = box[sB + x1];

            dst[row * W + col] = blend(x, y, x0, x1, y0, y1, Ia, Ib, Ic, Id);
        }
    } else {
        // Direct-gather fallback (rare: very large affine)
#pragma unroll
        for (int i = 0; i < ITERS; ++i) {
            const int row = rb + i * 4;
            float x, y;
            src_xy(a00, a01, a02, a10, a11, a12, row, col, x, y);

            const int x0u = (int)floorf(x);
            const int y0u = (int)floorf(y);
            const int x0 = min(max(x0u, 0), W - 1);
            const int x1 = min(max(x0u + 1, 0), W - 1);
            const int y0 = min(max(y0u, 0), H - 1);
            const int y1 = min(max(y0u + 1, 0), H - 1);

            const float Ia = __ldg(img + y0 * W + x0);
            const float Ib = __ldg(img + y1 * W + x0);
            const float Ic = __ldg(img + y0 * W + x1);
            const float Id = __ldg(img + y1 * W + x1);

            dst[row * W + col] = blend(x, y, x0, x1, y0, y1, Ia, Ib, Ic, Id);
        }
    }
}

extern "C" void kernel_launch(void* const* d_in, const int* in_sizes, int n_in,
                              void* d_out, int out_size)
{
    const float* stimuli = (const float*)d_in[0];
    const float* eye     = (const float*)d_in[1];
    float* out           = (float*)d_out;

    dim3 block(THREADS);
    dim3 grid(BLOCKS_X, NFRAMES);
    warp_bilinear_kernel<<<grid, block>>>(stimuli, eye, out);
}

// round 8
// speedup vs baseline: 1.0608x; 1.0608x over previous
#include <cuda_runtime.h>
#include <cstdint>

// Fixed shape: stimuli [4,32,304,608,1] fp32, eye [4,32,2,3]
constexpr int H  = 304;
constexpr int W  = 608;
constexpr int HW = H * W;
constexpr int NFRAMES = 128;

// Block tile: 32 cols x 16 rows, 256 threads (8 warps), warp = 8x4 px, ITERS=2.
constexpr int BTC = 32;
constexpr int BTR = 16;
constexpr int COL_TILES = W / BTC;                // 19
constexpr int ROW_TILES = H / BTR;                // 19
constexpr int BLOCKS_X  = COL_TILES * ROW_TILES;  // 361
constexpr int THREADS   = 256;

constexpr int PITCH = 121;    // compile-time, odd -> conflict-friendly
constexpr int MAXH  = 66;     // 121*66 = 7986 floats = 31944 B shared

__device__ __forceinline__ float lin_x(int col) {
    const float step_x = 2.0f / (float)(W - 1);
    return (col == W - 1) ? 1.0f
         : __fadd_rn(-1.0f, __fmul_rn((float)col, step_x));
}
__device__ __forceinline__ float lin_y(int row) {
    const float step_y = 2.0f / (float)(H - 1);
    return (row == H - 1) ? 1.0f
         : __fadd_rn(-1.0f, __fmul_rn((float)row, step_y));
}

__device__ __forceinline__ void src_xy(float a00, float a01, float a02,
                                       float a10, float a11, float a12,
                                       int row, int col, float& x, float& y) {
    const float xt = lin_x(col);
    const float yt = lin_y(row);
    const float Tx = __fadd_rn(__fmaf_rn(a01, yt, __fmul_rn(a00, xt)), a02);
    const float Ty = __fadd_rn(__fmaf_rn(a11, yt, __fmul_rn(a10, xt)), a12);
    x = __fmul_rn(__fadd_rn(Tx, 1.0f), (float)W * 0.5f);
    y = __fmul_rn(__fadd_rn(Ty, 1.0f), (float)H * 0.5f);
}

// Reference's exact FP sequence for weights + blend
__device__ __forceinline__ float blend(float x, float y,
                                       int x0, int x1, int y0, int y1,
                                       float Ia, float Ib, float Ic, float Id) {
    const float dx1 = __fsub_rn((float)x1, x);
    const float dx0 = __fsub_rn(x, (float)x0);
    const float dy1 = __fsub_rn((float)y1, y);
    const float dy0 = __fsub_rn(y, (float)y0);
    const float wa = __fmul_rn(dx1, dy1);
    const float wb = __fmul_rn(dx1, dy0);
    const float wc = __fmul_rn(dx0, dy1);
    const float wd = __fmul_rn(dx0, dy0);
    const float p1 = __fmul_rn(wa, Ia);
    const float p2 = __fmul_rn(wb, Ib);
    const float p3 = __fmul_rn(wc, Ic);
    const float p4 = __fmul_rn(wd, Id);
    return __fadd_rn(__fadd_rn(__fadd_rn(p1, p2), p3), p4);
}

__global__ __launch_bounds__(THREADS) void warp_bilinear_kernel(
    const float* __restrict__ stimuli,
    const float* __restrict__ eye,
    float* __restrict__ out)
{
    __shared__ float box[PITCH * MAXH];

    const int n  = blockIdx.y;
    const int bt = blockIdx.x;
    const int rt = bt / COL_TILES;
    const int ct = bt - rt * COL_TILES;
    const int col0 = ct * BTC;
    const int row0 = rt * BTR;

    const int wid  = threadIdx.x >> 5;
    const int lane = threadIdx.x & 31;

    const float* a = eye + (size_t)n * 6;
    const float a00 = __ldg(a + 0);
    const float a01 = __ldg(a + 1);
    const float a02 = __ldg(a + 2);
    const float a10 = __ldg(a + 3);
    const float a11 = __ldg(a + 4);
    const float a12 = __ldg(a + 5);

    const float* __restrict__ img = stimuli + (size_t)n * HW;
    float* __restrict__       dst = out     + (size_t)n * HW;

    // Warp layout over the 32x16 tile: 4 warps across x, 2 down y.
    const int col = col0 + (wid & 3) * 8 + (lane & 7);
    const int rb  = row0 + (wid >> 2) * 8 + (lane >> 3);

    // Hoisted per-thread invariants (col fixed)
    const float xt    = lin_x(col);
    const float a00xt = __fmul_rn(a00, xt);
    const float a10xt = __fmul_rn(a10, xt);

    // ---- Source bbox from the 4 tile corners (block-uniform) ----
    float cx0, cy0, cx1, cy1, cx2, cy2, cx3, cy3;
    src_xy(a00, a01, a02, a10, a11, a12, row0,           col0,           cx0, cy0);
    src_xy(a00, a01, a02, a10, a11, a12, row0,           col0 + BTC - 1, cx1, cy1);
    src_xy(a00, a01, a02, a10, a11, a12, row0 + BTR - 1, col0,           cx2, cy2);
    src_xy(a00, a01, a02, a10, a11, a12, row0 + BTR - 1, col0 + BTC - 1, cx3, cy3);

    const float xmin = fminf(fminf(cx0, cx1), fminf(cx2, cx3));
    const float xmax = fmaxf(fmaxf(cx0, cx1), fmaxf(cx2, cx3));
    const float ymin = fminf(fminf(cy0, cy1), fminf(cy2, cy3));
    const float ymax = fmaxf(fmaxf(cy0, cy1), fmaxf(cy2, cy3));

    const int bx0 = min(max((int)floorf(xmin) - 1, 0), W - 1);
    const int bx1 = min(max((int)floorf(xmax) + 2, 0), W - 1);
    const int by0 = min(max((int)floorf(ymin) - 1, 0), H - 1);
    const int by1 = min(max((int)floorf(ymax) + 2, 0), H - 1);

    const int bw = bx1 - bx0 + 1;
    const int bh = by1 - by0 + 1;
    const bool use_smem = (bw <= PITCH) && (bh <= MAXH);

    if (use_smem) {
        // ---- Staging: 8 warps over bh rows; 4 predicated column steps ----
        const int c0 = lane, c1 = lane + 32, c2 = lane + 64, c3 = lane + 96;
        for (int r = wid; r < bh; r += 8) {
            const float* srow = img + (by0 + r) * W + bx0;
            float* drow = box + r * PITCH;
            if (c0 < bw) drow[c0] = __ldg(srow + c0);
            if (c1 < bw) drow[c1] = __ldg(srow + c1);
            if (c2 < bw) drow[c2] = __ldg(srow + c2);
            if (c3 < bw) drow[c3] = __ldg(srow + c3);
        }
        __syncthreads();

        const int base = -(by0 * PITCH + bx0);   // block-uniform

#pragma unroll
        for (int i = 0; i < 2; ++i) {
            const int row = rb + i * 4;
            const float yt = lin_y(row);
            const float Tx = __fadd_rn(__fmaf_rn(a01, yt, a00xt), a02);
            const float Ty = __fadd_rn(__fmaf_rn(a11, yt, a10xt), a12);
            const float x  = __fmul_rn(__fadd_rn(Tx, 1.0f), (float)W * 0.5f);
            const float y  = __fmul_rn(__fadd_rn(Ty, 1.0f), (float)H * 0.5f);

            const int x0u = (int)floorf(x);
            const int y0u = (int)floorf(y);
            const int x0 = min(max(x0u, 0), W - 1);
            const int x1 = min(max(x0u + 1, 0), W - 1);
            const int y0 = min(max(y0u, 0), H - 1);
            const int y1 = min(max(y0u + 1, 0), H - 1);

            const int sA = y0 * PITCH + base;
            const int sB = y1 * PITCH + base;

            const float Ia = box[sA + x0];
            const float Ib = box[sB + x0];
            const float Ic = box[sA + x1];
            const float Id = box[sB + x1];

            dst[row * W + col] = blend(x, y, x0, x1, y0, y1, Ia, Ib, Ic, Id);
        }
    } else {
        // Direct-gather fallback (rare: very large affine) — R5 layout/speed
#pragma unroll
        for (int i = 0; i < 2; ++i) {
            const int row = rb + i * 4;
            const float yt = lin_y(row);
            const float Tx = __fadd_rn(__fmaf_rn(a01, yt, a00xt), a02);
            const float Ty = __fadd_rn(__fmaf_rn(a11, yt, a10xt), a12);
            const float x  = __fmul_rn(__fadd_rn(Tx, 1.0f), (float)W * 0.5f);
            const float y  = __fmul_rn(__fadd_rn(Ty, 1.0f), (float)H * 0.5f);

            const int x0u = (int)floorf(x);
            const int y0u = (int)floorf(y);
            const int x0 = min(max(x0u, 0), W - 1);
            const int x1 = min(max(x0u + 1, 0), W - 1);
            const int y0 = min(max(y0u, 0), H - 1);
            const int y1 = min(max(y0u + 1, 0), H - 1);

            const float Ia = __ldg(img + y0 * W + x0);
            const float Ib = __ldg(img + y1 * W + x0);
            const float Ic = __ldg(img + y0 * W + x1);
            const float Id = __ldg(img + y1 * W + x1);

            dst[row * W + col] = blend(x, y, x0, x1, y0, y1, Ia, Ib, Ic, Id);
        }
    }
}

extern "C" void kernel_launch(void* const* d_in, const int* in_sizes, int n_in,
                              void* d_out, int out_size)
{
    const float* stimuli = (const float*)d_in[0];
    const float* eye     = (const float*)d_in[1];
    float* out           = (float*)d_out;

    dim3 block(THREADS);
    dim3 grid(BLOCKS_X, NFRAMES);
    warp_bilinear_kernel<<<grid, block>>>(stimuli, eye, out);
}

// round 9
// speedup vs baseline: 1.8949x; 1.7864x over previous
#include <cuda_runtime.h>
#include <cstdint>

// Fixed shape: stimuli [4,32,304,608,1] fp32, eye [4,32,2,3]
constexpr int H  = 304;
constexpr int W  = 608;
constexpr int HW = H * W;
constexpr int NFRAMES = 128;

// Warp output tile: 8 cols x 4 rows per iteration, 4 iterations (8x16 px).
constexpr int TCOLS = 8;
constexpr int TROWS = 4;
constexpr int ITERS = 4;
constexpr int COL_TILES = W / TCOLS;               // 76
constexpr int ROW_TILES = H / (TROWS * ITERS);     // 19
constexpr int WARPS_PER_FRAME = COL_TILES * ROW_TILES;  // 1444
constexpr int WARPS_PER_BLOCK = 4;                 // 128 threads
constexpr int BLOCKS_X = WARPS_PER_FRAME / WARPS_PER_BLOCK;  // 361

__global__ __launch_bounds__(WARPS_PER_BLOCK * 32) void warp_bilinear_kernel(
    const float* __restrict__ stimuli,
    const float* __restrict__ eye,
    float* __restrict__ out)
{
    const int n    = blockIdx.y;
    const int warp = blockIdx.x * WARPS_PER_BLOCK + (threadIdx.x >> 5);
    const int lane = threadIdx.x & 31;

    const int rt = warp / COL_TILES;
    const int ct = warp - rt * COL_TILES;

    const int col   = ct * TCOLS + (lane & (TCOLS - 1));
    const int rbase = rt * (TROWS * ITERS) + (lane >> 3);

    const float* a = eye + (size_t)n * 6;
    const float a00 = __ldg(a + 0);
    const float a01 = __ldg(a + 1);
    const float a02 = __ldg(a + 2);
    const float a10 = __ldg(a + 3);
    const float a11 = __ldg(a + 4);
    const float a12 = __ldg(a + 5);

    // jnp.linspace(-1,1,n): v[i] = fl(-1 + fl(i*step)), endpoint exactly 1.0
    const float step_x = 2.0f / (float)(W - 1);
    const float step_y = 2.0f / (float)(H - 1);
    const float xt = (col == W - 1) ? 1.0f
                   : __fadd_rn(-1.0f, __fmul_rn((float)col, step_x));

    const float a00xt = __fmul_rn(a00, xt);
    const float a10xt = __fmul_rn(a10, xt);

    const float* __restrict__ img = stimuli + (size_t)n * HW;
    float* __restrict__       dst = out     + (size_t)n * HW;

    // ---- Phase 1: coords + all 16 gather loads in flight ----
    float xv[ITERS], yv[ITERS];
    float x0f[ITERS], x1f[ITERS], y0f[ITERS], y1f[ITERS];
    float Ia[ITERS], Ib[ITERS], Ic[ITERS], Id[ITERS];

#pragma unroll
    for (int i = 0; i < ITERS; ++i) {
        const int row = rbase + i * TROWS;
        const float yt = (row == H - 1) ? 1.0f
                       : __fadd_rn(-1.0f, __fmul_rn((float)row, step_y));

        const float Tx = __fadd_rn(__fmaf_rn(a01, yt, a00xt), a02);
        const float Ty = __fadd_rn(__fmaf_rn(a11, yt, a10xt), a12);

        const float x = __fmul_rn(__fadd_rn(Tx, 1.0f), (float)W * 0.5f);
        const float y = __fmul_rn(__fadd_rn(Ty, 1.0f), (float)H * 0.5f);
        xv[i] = x;  yv[i] = y;

        // float-domain clamps: floor values are integer-exact, so these bits
        // equal the reference's int clamp + cast
        const float fx0 = floorf(x);
        const float fy0 = floorf(y);
        x0f[i] = fminf(fmaxf(fx0, 0.0f), (float)(W - 1));
        x1f[i] = fminf(fmaxf(__fadd_rn(fx0, 1.0f), 0.0f), (float)(W - 1));
        y0f[i] = fminf(fmaxf(fy0, 0.0f), (float)(H - 1));
        y1f[i] = fminf(fmaxf(__fadd_rn(fy0, 1.0f), 0.0f), (float)(H - 1));

        const int x0 = (int)x0f[i];
        const int x1 = (int)x1f[i];
        const int y0 = (int)y0f[i];
        const int y1 = (int)y1f[i];

        const int dx  = x1 - x0;          // 0 or 1
        const int dyW = (y1 - y0) * W;    // 0 or W

        const float* pA = img + y0 * W + x0;
        Ia[i] = __ldg(pA);
        Ic[i] = __ldg(pA + dx);
        Ib[i] = __ldg(pA + dyW);
        Id[i] = __ldg(pA + dyW + dx);
    }

    // ---- Phase 2: blend + store (reference-exact FP sequence) ----
#pragma unroll
    for (int i = 0; i < ITERS; ++i) {
        const int row = rbase + i * TROWS;

        const float dx1 = __fsub_rn(x1f[i], xv[i]);
        const float dx0 = __fsub_rn(xv[i], x0f[i]);
        const float dy1 = __fsub_rn(y1f[i], yv[i]);
        const float dy0 = __fsub_rn(yv[i], y0f[i]);

        const float wa = __fmul_rn(dx1, dy1);
        const float wb = __fmul_rn(dx1, dy0);
        const float wc = __fmul_rn(dx0, dy1);
        const float wd = __fmul_rn(dx0, dy0);

        const float p1 = __fmul_rn(wa, Ia[i]);
        const float p2 = __fmul_rn(wb, Ib[i]);
        const float p3 = __fmul_rn(wc, Ic[i]);
        const float p4 = __fmul_rn(wd, Id[i]);
        dst[row * W + col] = __fadd_rn(__fadd_rn(__fadd_rn(p1, p2), p3), p4);
    }
}

extern "C" void kernel_launch(void* const* d_in, const int* in_sizes, int n_in,
                              void* d_out, int out_size)
{
    const float* stimuli = (const float*)d_in[0];
    const float* eye     = (const float*)d_in[1];
    float* out           = (float*)d_out;

    dim3 block(WARPS_PER_BLOCK * 32);
    dim3 grid(BLOCKS_X, NFRAMES);
    warp_bilinear_kernel<<<grid, block>>>(stimuli, eye, out);
}